// round 4
// baseline (speedup 1.0000x reference)
#include <cuda_runtime.h>
#include <cstdint>

#define Bb 256
#define Tt 512
#define Dd 128
#define Hh 128
#define Uu 64
#define Aa 10

// ---------------- device scratch (no allocs allowed) -------------------------
__device__ uint2 g_keys[1024];
__device__ float g_gum[1024][2560];          // [key j][b*10+a]
__device__ int   g_act2[Tt * Bb];            // [t*256+b]
__device__ float g_gi[(size_t)Bb * Tt * 384]; // [(b*512+t)*384 + g]

// ---------------- Threefry-2x32 (JAX-exact) ----------------------------------
__device__ __forceinline__ void tf2x32(uint32_t k0, uint32_t k1,
                                       uint32_t x0, uint32_t x1,
                                       uint32_t &o0, uint32_t &o1) {
  uint32_t k2 = k0 ^ k1 ^ 0x1BD11BDAu;
#define R_(r) { x0 += x1; x1 = (x1 << (r)) | (x1 >> (32 - (r))); x1 ^= x0; }
  x0 += k0; x1 += k1;
  R_(13) R_(15) R_(26) R_(6)  x0 += k1; x1 += k2 + 1u;
  R_(17) R_(29) R_(16) R_(24) x0 += k2; x1 += k0 + 2u;
  R_(13) R_(15) R_(26) R_(6)  x0 += k0; x1 += k1 + 3u;
  R_(17) R_(29) R_(16) R_(24) x0 += k1; x1 += k2 + 4u;
  R_(13) R_(15) R_(26) R_(6)  x0 += k2; x1 += k0 + 5u;
#undef R_
  o0 = x0; o1 = x1;
}

// bits -> gumbel, matching jax uniform(tiny,1) then -log(-log u); logs in
// double so forced fast-math cannot perturb the argmax.
__device__ __forceinline__ float b2g(uint32_t bits) {
  float f = __uint_as_float((bits >> 9) | 0x3f800000u) - 1.0f;
  double u = (double)fmaxf(f, 1.17549435e-38f);
  return (float)(-log(-log(u)));
}

__device__ __forceinline__ float sigm(float x) { return 1.0f / (1.0f + expf(-x)); }

// ---------------- K0: split keys (partitionable / foldlike) ------------------
// key[j] = (o0, o1) of threefry(key=(0,42), counter=(hi=0, lo=j))
__global__ void k_keys() {
  int j = blockIdx.x * 256 + threadIdx.x;
  if (j >= 1024) return;
  uint32_t o0, o1;
  tf2x32(0u, 42u, 0u, (uint32_t)j, o0, o1);
  g_keys[j] = make_uint2(o0, o1);
}

// ---------------- K1: gumbel noise (partitionable random_bits: o0 ^ o1) ------
__global__ void k_gum() {
  int j = blockIdx.x;
  uint2 key = g_keys[j];
  for (int p = threadIdx.x; p < 2560; p += 256) {
    uint32_t o0, o1;
    tf2x32(key.x, key.y, 0u, (uint32_t)p, o0, o1);
    g_gum[j][p] = b2g(o0 ^ o1);
  }
}

// ---------------- K2: gi = x @ w_ih^T + b_ih (+ b_hh folded for r,z) ---------
__global__ __launch_bounds__(128, 1) void k_gi(const float* __restrict__ x,
                                               const float* __restrict__ wih,
                                               const float* __restrict__ bih,
                                               const float* __restrict__ bhh) {
  extern __shared__ float sm[];
  float* xs = sm;                 // 128 rows x 132 (pad)
  float* ws = xs + 128 * 132;     // 128 x 128 weight tile
  float* sb = ws + 128 * 128;     // 128 x 132 store staging
  float* bs = sb + 128 * 132;     // 128 bias
  int tid = threadIdx.x;
  size_t row0 = (size_t)blockIdx.x * 128;

  const float4* xg = (const float4*)(x + row0 * Dd);
  for (int i = tid; i < 128 * 32; i += 128) {
    int r = i >> 5, c = i & 31;
    ((float4*)(xs + r * 132))[c] = xg[i];
  }
  __syncthreads();

  for (int pass = 0; pass < 3; pass++) {
    for (int i = tid; i < 128 * 32; i += 128)
      ((float4*)ws)[i] = ((const float4*)(wih + (size_t)pass * 128 * Dd))[i];
    {
      int g = pass * 128 + tid;
      bs[tid] = bih[g] + (g < 256 ? bhh[g] : 0.0f);
    }
    __syncthreads();

    float acc[128];
#pragma unroll
    for (int j = 0; j < 128; j++) acc[j] = bs[j];
    const float4* xr = (const float4*)(xs + tid * 132);
    for (int c = 0; c < 32; c++) {
      float4 xv = xr[c];
#pragma unroll
      for (int j = 0; j < 128; j++) {
        float4 wv = ((const float4*)ws)[j * 32 + c];
        acc[j] += xv.x * wv.x + xv.y * wv.y + xv.z * wv.z + xv.w * wv.w;
      }
    }
#pragma unroll
    for (int j = 0; j < 128; j += 4)
      ((float4*)(sb + tid * 132))[j >> 2] = make_float4(acc[j], acc[j+1], acc[j+2], acc[j+3]);
    __syncthreads();
    for (int i = tid; i < 128 * 128; i += 128) {
      int r = i >> 7, c = i & 127;
      g_gi[(row0 + r) * 384 + pass * 128 + c] = sb[r * 132 + c];
    }
    __syncthreads();
  }
}

// ---------------- K3: agent-2 actions (x-only path) --------------------------
__global__ __launch_bounds__(128, 1) void k_act2(const float* __restrict__ x,
                                                 const float* __restrict__ w1,
                                                 const float* __restrict__ b1,
                                                 const float* __restrict__ w2,
                                                 const float* __restrict__ b2) {
  extern __shared__ float sm[];
  float* xs  = sm;                 // 128 x 132
  float* w1s = xs + 128 * 132;     // 64 x 128
  float* w2s = w1s + 64 * 128;     // 640
  float* b1s = w2s + 640;          // 64
  float* b2s = b1s + 64;           // 12
  int tid = threadIdx.x;
  size_t row0 = (size_t)blockIdx.x * 128;

  const float4* xg = (const float4*)(x + row0 * Dd);
  for (int i = tid; i < 128 * 32; i += 128) {
    int r = i >> 5, c = i & 31;
    ((float4*)(xs + r * 132))[c] = xg[i];
  }
  for (int i = tid; i < 64 * 32; i += 128) ((float4*)w1s)[i] = ((const float4*)w1)[i];
  for (int i = tid; i < 640; i += 128) w2s[i] = w2[i];
  if (tid < 64) b1s[tid] = b1[tid];
  if (tid < 10) b2s[tid] = b2[tid];
  __syncthreads();

  float acc[64];
#pragma unroll
  for (int u = 0; u < 64; u++) acc[u] = b1s[u];
  const float4* xr = (const float4*)(xs + tid * 132);
  for (int c = 0; c < 32; c++) {
    float4 xv = xr[c];
#pragma unroll
    for (int u = 0; u < 64; u++) {
      float4 wv = ((const float4*)w1s)[u * 32 + c];
      acc[u] += xv.x * wv.x + xv.y * wv.y + xv.z * wv.z + xv.w * wv.w;
    }
  }
#pragma unroll
  for (int u = 0; u < 64; u++) acc[u] = tanhf(acc[u]);

  size_t row = row0 + tid;
  int b = (int)(row >> 9), t = (int)(row & 511);
  const float* gg = g_gum[2 * t + 1] + b * 10;
  float best = -1e30f; int bi = 0;
#pragma unroll
  for (int a = 0; a < 10; a++) {
    float lg = b2s[a];
#pragma unroll
    for (int u = 0; u < 64; u++) lg += acc[u] * w2s[a * 64 + u];
    float v = lg + gg[a];
    if (v > best) { best = v; bi = a; }
  }
  g_act2[t * 256 + b] = bi;
}

// ---------------- K4: persistent recurrent kernel ----------------------------
// 128 CTAs x 128 threads; CTA owns batches 2*blk, 2*blk+1; thread d owns dim d.
__global__ __launch_bounds__(128, 1) void k_recur(const int* __restrict__ mask,
                                                  const float* __restrict__ whh,
                                                  const float* __restrict__ bhh,
                                                  const float* __restrict__ a1w1,
                                                  const float* __restrict__ a1b1,
                                                  const float* __restrict__ a1w2,
                                                  const float* __restrict__ a1b2,
                                                  float* __restrict__ out) {
  extern __shared__ float sm[];
  float* ws  = sm;              // 384*128 = 49152  (w_hh, row-major [g][k])
  float* w1T = ws + 49152;      // 128*64: w1T[k*64+u] = a1_w1[u][k]
  float* wt  = w1T + 8192;      // [2][128]  mean then weighted
  float* ps  = wt + 256;        // [2][128]  zarg partials / mask partials
  float* lgp = ps + 256;        // [warp 2][b 2][a 10] = 40
  int*   ais = (int*)(lgp + 40);// a1[2], a2[2]

  int tid = threadIdx.x;
  int b0 = blockIdx.x * 2, b1 = b0 + 1;
  float* outh = out + (size_t)Bb * Hh;  // h_all base

  for (int i = tid; i < 49152; i += 128) ws[i] = whh[i];
  for (int i = tid; i < 8192; i += 128) {
    int u = i >> 7, k = i & 127;
    w1T[k * 64 + u] = a1w1[i];
  }
  float bhn = bhh[256 + tid];
  float b1r = 0.0f, w2c[10];
#pragma unroll
  for (int a = 0; a < 10; a++) w2c[a] = 0.0f;
  if (tid < 64) {
    b1r = a1b1[tid];
#pragma unroll
    for (int a = 0; a < 10; a++) w2c[a] = a1w2[a * 64 + tid];
  }
  float b2r[10];
#pragma unroll
  for (int a = 0; a < 10; a++) b2r[a] = 0.0f;
  if (tid < 2) {
#pragma unroll
    for (int a = 0; a < 10; a++) b2r[a] = a1b2[a];
  }
  __syncthreads();

  float h[2];
  float buf[2][10];
#pragma unroll
  for (int bb = 0; bb < 2; bb++)
#pragma unroll
    for (int s = 0; s < 10; s++) buf[bb][s] = 0.0f;

  // t = 0: weighted = 0, gh = b_hh (biases folded into g_gi for r,z)
  {
    size_t r0 = ((size_t)b0 * 512) * 384, r1 = ((size_t)b1 * 512) * 384;
#pragma unroll
    for (int bb = 0; bb < 2; bb++) {
      size_t rr = bb ? r1 : r0;
      float gir = g_gi[rr + tid], giz = g_gi[rr + 128 + tid], gin = g_gi[rr + 256 + tid];
      float r = sigm(gir), z = sigm(giz);
      float n = tanhf(gin + r * bhn);
      h[bb] = (1.0f - z) * n;             // z * weighted(=0)
      outh[((size_t)(bb ? b1 : b0) * 512 + 0) * 128 + tid] = h[bb];
    }
  }

  for (int t = 1; t < 512; t++) {
    // prefetch gi, gumbel(agent1), act2
    size_t r0 = ((size_t)b0 * 512 + t) * 384, r1 = ((size_t)b1 * 512 + t) * 384;
    float gir0 = g_gi[r0 + tid], giz0 = g_gi[r0 + 128 + tid], gin0 = g_gi[r0 + 256 + tid];
    float gir1 = g_gi[r1 + tid], giz1 = g_gi[r1 + 128 + tid], gin1 = g_gi[r1 + 256 + tid];
    float g1v[10];
#pragma unroll
    for (int a = 0; a < 10; a++) g1v[a] = 0.0f;
    if (tid < 2) {
      int bb = tid ? b1 : b0;
      const float* gg = g_gum[2 * t] + bb * 10;
#pragma unroll
      for (int a = 0; a < 10; a++) g1v[a] = gg[a];
      ais[2 + tid] = g_act2[t * 256 + bb];
    }

    // shift buf (append h_{t-1}), fresh sum, mean -> wt
#pragma unroll
    for (int bb = 0; bb < 2; bb++) {
      float s = h[bb];
#pragma unroll
      for (int s9 = 0; s9 < 9; s9++) { buf[bb][s9] = buf[bb][s9 + 1]; s += buf[bb][s9]; }
      buf[bb][9] = h[bb];
      wt[bb * 128 + tid] = s / 10.0f;
    }
    __syncthreads();

    // zarg partials: u = tid&63, half = tid>>6
    {
      int u = tid & 63, hf = tid >> 6;
      const float* mp0 = wt + hf * 64;
      const float* mp1 = wt + 128 + hf * 64;
      float p0 = 0.0f, p1 = 0.0f;
#pragma unroll
      for (int k = 0; k < 64; k++) {
        float w = w1T[(hf * 64 + k) * 64 + u];
        p0 += mp0[k] * w; p1 += mp1[k] * w;
      }
      ps[tid] = p0; ps[128 + tid] = p1;
    }
    __syncthreads();

    if (tid < 64) {
      float z0 = tanhf(ps[tid] + ps[tid + 64] + b1r);
      float z1 = tanhf(ps[128 + tid] + ps[128 + tid + 64] + b1r);
      float lp[20];
#pragma unroll
      for (int a = 0; a < 10; a++) { lp[a] = z0 * w2c[a]; lp[10 + a] = z1 * w2c[a]; }
#pragma unroll
      for (int off = 16; off > 0; off >>= 1)
#pragma unroll
        for (int a = 0; a < 20; a++) lp[a] += __shfl_down_sync(0xffffffffu, lp[a], off);
      if ((tid & 31) == 0) {
        int w = tid >> 5;
#pragma unroll
        for (int a = 0; a < 20; a++) lgp[w * 20 + a] = lp[a];
      }
    }
    __syncthreads();

    if (tid < 2) {
      float best = -1e30f; int bi = 0;
#pragma unroll
      for (int a = 0; a < 10; a++) {
        float v = lgp[tid * 10 + a] + lgp[20 + tid * 10 + a] + b2r[a] + g1v[a];
        if (v > best) { best = v; bi = a; }
      }
      ais[tid] = bi;
    }
    __syncthreads();

    int a1_0 = ais[0], a1_1 = ais[1], a2_0 = ais[2], a2_1 = ais[3];
    float wtd0, wtd1;
    {
      float sa = buf[0][0], sb2 = buf[0][0];
#pragma unroll
      for (int s = 1; s < 10; s++) { if (a1_0 == s) sa = buf[0][s]; if (a2_0 == s) sb2 = buf[0][s]; }
      wtd0 = 0.25f * (sa + sb2) + 0.5f * h[0];
      float sc = buf[1][0], sd = buf[1][0];
#pragma unroll
      for (int s = 1; s < 10; s++) { if (a1_1 == s) sc = buf[1][s]; if (a2_1 == s) sd = buf[1][s]; }
      wtd1 = 0.25f * (sc + sd) + 0.5f * h[1];
    }
    wt[tid] = wtd0; wt[128 + tid] = wtd1;
    __syncthreads();

    // GEMV gh = weighted @ w_hh^T, rows (tid, tid+128, tid+256), both batches
    float ar0 = 0, az0 = 0, an0 = 0, ar1 = 0, az1 = 0, an1 = 0;
    int rot = tid & 31;
    const float4* ws4 = (const float4*)ws;
    const float4* v4a = (const float4*)wt;
    const float4* v4b = (const float4*)(wt + 128);
#pragma unroll 8
    for (int c = 0; c < 32; c++) {
      int cc = (c + rot) & 31;
      float4 wr = ws4[tid * 32 + cc];
      float4 wz = ws4[(tid + 128) * 32 + cc];
      float4 wn = ws4[(tid + 256) * 32 + cc];
      float4 v0 = v4a[cc], v1 = v4b[cc];
      ar0 += wr.x * v0.x + wr.y * v0.y + wr.z * v0.z + wr.w * v0.w;
      ar1 += wr.x * v1.x + wr.y * v1.y + wr.z * v1.z + wr.w * v1.w;
      az0 += wz.x * v0.x + wz.y * v0.y + wz.z * v0.z + wz.w * v0.w;
      az1 += wz.x * v1.x + wz.y * v1.y + wz.z * v1.z + wz.w * v1.w;
      an0 += wn.x * v0.x + wn.y * v0.y + wn.z * v0.z + wn.w * v0.w;
      an1 += wn.x * v1.x + wn.y * v1.y + wn.z * v1.z + wn.w * v1.w;
    }
    {
      float r = sigm(gir0 + ar0), z = sigm(giz0 + az0);
      float n = tanhf(gin0 + r * (an0 + bhn));
      h[0] = (1.0f - z) * n + z * wtd0;
      float r2 = sigm(gir1 + ar1), z2 = sigm(giz1 + az1);
      float n2 = tanhf(gin1 + r2 * (an1 + bhn));
      h[1] = (1.0f - z2) * n2 + z2 * wtd1;
    }
    outh[((size_t)b0 * 512 + t) * 128 + tid] = h[0];
    outh[((size_t)b1 * 512 + t) * 128 + tid] = h[1];
    __syncthreads();  // protect wt for next iter
  }

  // last_out via mask
  {
    int p0 = 0, p1 = 0;
    for (int t = tid; t < 512; t += 128) { p0 += mask[b0 * 512 + t]; p1 += mask[b1 * 512 + t]; }
    ps[tid] = (float)p0; ps[128 + tid] = (float)p1;
    __syncthreads();
    if (tid < 2) {
      const float* pp = ps + tid * 128;
      int s = 0;
      for (int i = 0; i < 128; i++) s += (int)pp[i];
      ais[tid] = s - 1;
    }
    __syncthreads();
    int li0 = ais[0], li1 = ais[1];
    out[b0 * 128 + tid] = outh[((size_t)b0 * 512 + li0) * 128 + tid];
    out[b1 * 128 + tid] = outh[((size_t)b1 * 512 + li1) * 128 + tid];
  }
}

// ---------------- launcher ---------------------------------------------------
extern "C" void kernel_launch(void* const* d_in, const int* in_sizes, int n_in,
                              void* d_out, int out_size) {
  const float* x    = (const float*)d_in[0];
  const int*   mask = (const int*)d_in[1];
  const float* wih  = (const float*)d_in[2];
  const float* whh  = (const float*)d_in[3];
  const float* bih  = (const float*)d_in[4];
  const float* bhh  = (const float*)d_in[5];
  const float* a1w1 = (const float*)d_in[6];
  const float* a1b1 = (const float*)d_in[7];
  const float* a1w2 = (const float*)d_in[8];
  const float* a1b2 = (const float*)d_in[9];
  const float* a2w1 = (const float*)d_in[10];
  const float* a2b1 = (const float*)d_in[11];
  const float* a2w2 = (const float*)d_in[12];
  const float* a2b2 = (const float*)d_in[13];
  float* out = (float*)d_out;

  const int smem_gi = (128 * 132 + 128 * 128 + 128 * 132 + 128) * 4;
  const int smem_a2 = (128 * 132 + 64 * 128 + 640 + 64 + 16) * 4;
  const int smem_rc = (49152 + 8192 + 256 + 256 + 40) * 4 + 16;

  cudaFuncSetAttribute(k_gi,    cudaFuncAttributeMaxDynamicSharedMemorySize, smem_gi);
  cudaFuncSetAttribute(k_act2,  cudaFuncAttributeMaxDynamicSharedMemorySize, smem_a2);
  cudaFuncSetAttribute(k_recur, cudaFuncAttributeMaxDynamicSharedMemorySize, smem_rc);

  k_keys<<<4, 256>>>();
  k_gum<<<1024, 256>>>();
  k_act2<<<1024, 128, smem_a2>>>(x, a2w1, a2b1, a2w2, a2b2);
  k_gi<<<1024, 128, smem_gi>>>(x, wih, bih, bhh);
  k_recur<<<128, 128, smem_rc>>>(mask, whh, bhh, a1w1, a1b1, a1w2, a1b2, out);
}

// round 5
// speedup vs baseline: 1.0004x; 1.0004x over previous
#include <cuda_runtime.h>
#include <cstdint>

#define Bb 256
#define Tt 512
#define Dd 128
#define Hh 128
#define Uu 64
#define Aa 10

// ---------------- device scratch (no allocs allowed) -------------------------
__device__ uint2 g_keys[1024];
__device__ float g_gum[1024][2560];          // [key j][b*10+a]
__device__ int   g_act2[Tt * Bb];            // [t*256+b]
__device__ float g_gi[(size_t)Bb * Tt * 384]; // [(b*512+t)*384 + g]

// ---------------- Threefry-2x32 (JAX-exact) ----------------------------------
__device__ __forceinline__ void tf2x32(uint32_t k0, uint32_t k1,
                                       uint32_t x0, uint32_t x1,
                                       uint32_t &o0, uint32_t &o1) {
  uint32_t k2 = k0 ^ k1 ^ 0x1BD11BDAu;
#define R_(r) { x0 += x1; x1 = (x1 << (r)) | (x1 >> (32 - (r))); x1 ^= x0; }
  x0 += k0; x1 += k1;
  R_(13) R_(15) R_(26) R_(6)  x0 += k1; x1 += k2 + 1u;
  R_(17) R_(29) R_(16) R_(24) x0 += k2; x1 += k0 + 2u;
  R_(13) R_(15) R_(26) R_(6)  x0 += k0; x1 += k1 + 3u;
  R_(17) R_(29) R_(16) R_(24) x0 += k1; x1 += k2 + 4u;
  R_(13) R_(15) R_(26) R_(6)  x0 += k2; x1 += k0 + 5u;
#undef R_
  o0 = x0; o1 = x1;
}

// bits -> gumbel, matching jax uniform(tiny,1) then -log(-log u); logs in
// double so forced fast-math cannot perturb the argmax.
__device__ __forceinline__ float b2g(uint32_t bits) {
  float f = __uint_as_float((bits >> 9) | 0x3f800000u) - 1.0f;
  double u = (double)fmaxf(f, 1.17549435e-38f);
  return (float)(-log(-log(u)));
}

__device__ __forceinline__ float sigm(float x) { return 1.0f / (1.0f + expf(-x)); }

// ---------------- K0: split keys (partitionable / foldlike) ------------------
// key[j] = (o0, o1) of threefry(key=(0,42), counter=(hi=0, lo=j))
__global__ void k_keys() {
  int j = blockIdx.x * 256 + threadIdx.x;
  if (j >= 1024) return;
  uint32_t o0, o1;
  tf2x32(0u, 42u, 0u, (uint32_t)j, o0, o1);
  g_keys[j] = make_uint2(o0, o1);
}

// ---------------- K1: gumbel noise (partitionable random_bits: o0 ^ o1) ------
__global__ void k_gum() {
  int j = blockIdx.x;
  uint2 key = g_keys[j];
  for (int p = threadIdx.x; p < 2560; p += 256) {
    uint32_t o0, o1;
    tf2x32(key.x, key.y, 0u, (uint32_t)p, o0, o1);
    g_gum[j][p] = b2g(o0 ^ o1);
  }
}

// ---------------- K2: gi = x @ w_ih^T + b_ih (+ b_hh folded for r,z) ---------
__global__ __launch_bounds__(128, 1) void k_gi(const float* __restrict__ x,
                                               const float* __restrict__ wih,
                                               const float* __restrict__ bih,
                                               const float* __restrict__ bhh) {
  extern __shared__ float sm[];
  float* xs = sm;                 // 128 rows x 132 (pad)
  float* ws = xs + 128 * 132;     // 128 x 128 weight tile
  float* sb = ws + 128 * 128;     // 128 x 132 store staging
  float* bs = sb + 128 * 132;     // 128 bias
  int tid = threadIdx.x;
  size_t row0 = (size_t)blockIdx.x * 128;

  const float4* xg = (const float4*)(x + row0 * Dd);
  for (int i = tid; i < 128 * 32; i += 128) {
    int r = i >> 5, c = i & 31;
    ((float4*)(xs + r * 132))[c] = xg[i];
  }
  __syncthreads();

  for (int pass = 0; pass < 3; pass++) {
    for (int i = tid; i < 128 * 32; i += 128)
      ((float4*)ws)[i] = ((const float4*)(wih + (size_t)pass * 128 * Dd))[i];
    {
      int g = pass * 128 + tid;
      bs[tid] = bih[g] + (g < 256 ? bhh[g] : 0.0f);
    }
    __syncthreads();

    float acc[128];
#pragma unroll
    for (int j = 0; j < 128; j++) acc[j] = bs[j];
    const float4* xr = (const float4*)(xs + tid * 132);
    for (int c = 0; c < 32; c++) {
      float4 xv = xr[c];
#pragma unroll
      for (int j = 0; j < 128; j++) {
        float4 wv = ((const float4*)ws)[j * 32 + c];
        acc[j] += xv.x * wv.x + xv.y * wv.y + xv.z * wv.z + xv.w * wv.w;
      }
    }
#pragma unroll
    for (int j = 0; j < 128; j += 4)
      ((float4*)(sb + tid * 132))[j >> 2] = make_float4(acc[j], acc[j+1], acc[j+2], acc[j+3]);
    __syncthreads();
    for (int i = tid; i < 128 * 128; i += 128) {
      int r = i >> 7, c = i & 127;
      g_gi[(row0 + r) * 384 + pass * 128 + c] = sb[r * 132 + c];
    }
    __syncthreads();
  }
}

// ---------------- K3: agent-2 actions (x-only path) --------------------------
__global__ __launch_bounds__(128, 1) void k_act2(const float* __restrict__ x,
                                                 const float* __restrict__ w1,
                                                 const float* __restrict__ b1,
                                                 const float* __restrict__ w2,
                                                 const float* __restrict__ b2) {
  extern __shared__ float sm[];
  float* xs  = sm;                 // 128 x 132
  float* w1s = xs + 128 * 132;     // 64 x 128
  float* w2s = w1s + 64 * 128;     // 640
  float* b1s = w2s + 640;          // 64
  float* b2s = b1s + 64;           // 12
  int tid = threadIdx.x;
  size_t row0 = (size_t)blockIdx.x * 128;

  const float4* xg = (const float4*)(x + row0 * Dd);
  for (int i = tid; i < 128 * 32; i += 128) {
    int r = i >> 5, c = i & 31;
    ((float4*)(xs + r * 132))[c] = xg[i];
  }
  for (int i = tid; i < 64 * 32; i += 128) ((float4*)w1s)[i] = ((const float4*)w1)[i];
  for (int i = tid; i < 640; i += 128) w2s[i] = w2[i];
  if (tid < 64) b1s[tid] = b1[tid];
  if (tid < 10) b2s[tid] = b2[tid];
  __syncthreads();

  float acc[64];
#pragma unroll
  for (int u = 0; u < 64; u++) acc[u] = b1s[u];
  const float4* xr = (const float4*)(xs + tid * 132);
  for (int c = 0; c < 32; c++) {
    float4 xv = xr[c];
#pragma unroll
    for (int u = 0; u < 64; u++) {
      float4 wv = ((const float4*)w1s)[u * 32 + c];
      acc[u] += xv.x * wv.x + xv.y * wv.y + xv.z * wv.z + xv.w * wv.w;
    }
  }
#pragma unroll
  for (int u = 0; u < 64; u++) acc[u] = tanhf(acc[u]);

  size_t row = row0 + tid;
  int b = (int)(row >> 9), t = (int)(row & 511);
  const float* gg = g_gum[2 * t + 1] + b * 10;
  float best = -1e30f; int bi = 0;
#pragma unroll
  for (int a = 0; a < 10; a++) {
    float lg = b2s[a];
#pragma unroll
    for (int u = 0; u < 64; u++) lg += acc[u] * w2s[a * 64 + u];
    float v = lg + gg[a];
    if (v > best) { best = v; bi = a; }
  }
  g_act2[t * 256 + b] = bi;
}

// ---------------- K4: persistent recurrent kernel ----------------------------
// 128 CTAs x 128 threads; CTA owns batches 2*blk, 2*blk+1; thread d owns dim d.
__global__ __launch_bounds__(128, 1) void k_recur(const int* __restrict__ mask,
                                                  const float* __restrict__ whh,
                                                  const float* __restrict__ bhh,
                                                  const float* __restrict__ a1w1,
                                                  const float* __restrict__ a1b1,
                                                  const float* __restrict__ a1w2,
                                                  const float* __restrict__ a1b2,
                                                  float* __restrict__ out) {
  extern __shared__ float sm[];
  float* ws  = sm;              // 384*128 = 49152  (w_hh, row-major [g][k])
  float* w1T = ws + 49152;      // 128*64: w1T[k*64+u] = a1_w1[u][k]
  float* wt  = w1T + 8192;      // [2][128]  mean then weighted
  float* ps  = wt + 256;        // [2][128]  zarg partials / mask partials
  float* lgp = ps + 256;        // [warp 2][b 2][a 10] = 40
  int*   ais = (int*)(lgp + 40);// a1[2], a2[2]

  int tid = threadIdx.x;
  int b0 = blockIdx.x * 2, b1 = b0 + 1;
  float* outh = out + (size_t)Bb * Hh;  // h_all base

  for (int i = tid; i < 49152; i += 128) ws[i] = whh[i];
  for (int i = tid; i < 8192; i += 128) {
    int u = i >> 7, k = i & 127;
    w1T[k * 64 + u] = a1w1[i];
  }
  float bhn = bhh[256 + tid];
  float b1r = 0.0f, w2c[10];
#pragma unroll
  for (int a = 0; a < 10; a++) w2c[a] = 0.0f;
  if (tid < 64) {
    b1r = a1b1[tid];
#pragma unroll
    for (int a = 0; a < 10; a++) w2c[a] = a1w2[a * 64 + tid];
  }
  float b2r[10];
#pragma unroll
  for (int a = 0; a < 10; a++) b2r[a] = 0.0f;
  if (tid < 2) {
#pragma unroll
    for (int a = 0; a < 10; a++) b2r[a] = a1b2[a];
  }
  __syncthreads();

  float h[2];
  float buf[2][10];
#pragma unroll
  for (int bb = 0; bb < 2; bb++)
#pragma unroll
    for (int s = 0; s < 10; s++) buf[bb][s] = 0.0f;

  // t = 0: weighted = 0, gh = b_hh (biases folded into g_gi for r,z)
  {
    size_t r0 = ((size_t)b0 * 512) * 384, r1 = ((size_t)b1 * 512) * 384;
#pragma unroll
    for (int bb = 0; bb < 2; bb++) {
      size_t rr = bb ? r1 : r0;
      float gir = g_gi[rr + tid], giz = g_gi[rr + 128 + tid], gin = g_gi[rr + 256 + tid];
      float r = sigm(gir), z = sigm(giz);
      float n = tanhf(gin + r * bhn);
      h[bb] = (1.0f - z) * n;             // z * weighted(=0)
      outh[((size_t)(bb ? b1 : b0) * 512 + 0) * 128 + tid] = h[bb];
    }
  }

  for (int t = 1; t < 512; t++) {
    // prefetch gi, gumbel(agent1), act2
    size_t r0 = ((size_t)b0 * 512 + t) * 384, r1 = ((size_t)b1 * 512 + t) * 384;
    float gir0 = g_gi[r0 + tid], giz0 = g_gi[r0 + 128 + tid], gin0 = g_gi[r0 + 256 + tid];
    float gir1 = g_gi[r1 + tid], giz1 = g_gi[r1 + 128 + tid], gin1 = g_gi[r1 + 256 + tid];
    float g1v[10];
#pragma unroll
    for (int a = 0; a < 10; a++) g1v[a] = 0.0f;
    if (tid < 2) {
      int bb = tid ? b1 : b0;
      const float* gg = g_gum[2 * t] + bb * 10;
#pragma unroll
      for (int a = 0; a < 10; a++) g1v[a] = gg[a];
      ais[2 + tid] = g_act2[t * 256 + bb];
    }

    // shift buf (append h_{t-1}), fresh sum, mean -> wt
#pragma unroll
    for (int bb = 0; bb < 2; bb++) {
      float s = h[bb];
#pragma unroll
      for (int s9 = 0; s9 < 9; s9++) { buf[bb][s9] = buf[bb][s9 + 1]; s += buf[bb][s9]; }
      buf[bb][9] = h[bb];
      wt[bb * 128 + tid] = s / 10.0f;
    }
    __syncthreads();

    // zarg partials: u = tid&63, half = tid>>6
    {
      int u = tid & 63, hf = tid >> 6;
      const float* mp0 = wt + hf * 64;
      const float* mp1 = wt + 128 + hf * 64;
      float p0 = 0.0f, p1 = 0.0f;
#pragma unroll
      for (int k = 0; k < 64; k++) {
        float w = w1T[(hf * 64 + k) * 64 + u];
        p0 += mp0[k] * w; p1 += mp1[k] * w;
      }
      ps[tid] = p0; ps[128 + tid] = p1;
    }
    __syncthreads();

    if (tid < 64) {
      float z0 = tanhf(ps[tid] + ps[tid + 64] + b1r);
      float z1 = tanhf(ps[128 + tid] + ps[128 + tid + 64] + b1r);
      float lp[20];
#pragma unroll
      for (int a = 0; a < 10; a++) { lp[a] = z0 * w2c[a]; lp[10 + a] = z1 * w2c[a]; }
#pragma unroll
      for (int off = 16; off > 0; off >>= 1)
#pragma unroll
        for (int a = 0; a < 20; a++) lp[a] += __shfl_down_sync(0xffffffffu, lp[a], off);
      if ((tid & 31) == 0) {
        int w = tid >> 5;
#pragma unroll
        for (int a = 0; a < 20; a++) lgp[w * 20 + a] = lp[a];
      }
    }
    __syncthreads();

    if (tid < 2) {
      float best = -1e30f; int bi = 0;
#pragma unroll
      for (int a = 0; a < 10; a++) {
        float v = lgp[tid * 10 + a] + lgp[20 + tid * 10 + a] + b2r[a] + g1v[a];
        if (v > best) { best = v; bi = a; }
      }
      ais[tid] = bi;
    }
    __syncthreads();

    int a1_0 = ais[0], a1_1 = ais[1], a2_0 = ais[2], a2_1 = ais[3];
    float wtd0, wtd1;
    {
      float sa = buf[0][0], sb2 = buf[0][0];
#pragma unroll
      for (int s = 1; s < 10; s++) { if (a1_0 == s) sa = buf[0][s]; if (a2_0 == s) sb2 = buf[0][s]; }
      wtd0 = 0.25f * (sa + sb2) + 0.5f * h[0];
      float sc = buf[1][0], sd = buf[1][0];
#pragma unroll
      for (int s = 1; s < 10; s++) { if (a1_1 == s) sc = buf[1][s]; if (a2_1 == s) sd = buf[1][s]; }
      wtd1 = 0.25f * (sc + sd) + 0.5f * h[1];
    }
    wt[tid] = wtd0; wt[128 + tid] = wtd1;
    __syncthreads();

    // GEMV gh = weighted @ w_hh^T, rows (tid, tid+128, tid+256), both batches
    float ar0 = 0, az0 = 0, an0 = 0, ar1 = 0, az1 = 0, an1 = 0;
    int rot = tid & 31;
    const float4* ws4 = (const float4*)ws;
    const float4* v4a = (const float4*)wt;
    const float4* v4b = (const float4*)(wt + 128);
#pragma unroll 8
    for (int c = 0; c < 32; c++) {
      int cc = (c + rot) & 31;
      float4 wr = ws4[tid * 32 + cc];
      float4 wz = ws4[(tid + 128) * 32 + cc];
      float4 wn = ws4[(tid + 256) * 32 + cc];
      float4 v0 = v4a[cc], v1 = v4b[cc];
      ar0 += wr.x * v0.x + wr.y * v0.y + wr.z * v0.z + wr.w * v0.w;
      ar1 += wr.x * v1.x + wr.y * v1.y + wr.z * v1.z + wr.w * v1.w;
      az0 += wz.x * v0.x + wz.y * v0.y + wz.z * v0.z + wz.w * v0.w;
      az1 += wz.x * v1.x + wz.y * v1.y + wz.z * v1.z + wz.w * v1.w;
      an0 += wn.x * v0.x + wn.y * v0.y + wn.z * v0.z + wn.w * v0.w;
      an1 += wn.x * v1.x + wn.y * v1.y + wn.z * v1.z + wn.w * v1.w;
    }
    {
      float r = sigm(gir0 + ar0), z = sigm(giz0 + az0);
      float n = tanhf(gin0 + r * (an0 + bhn));
      h[0] = (1.0f - z) * n + z * wtd0;
      float r2 = sigm(gir1 + ar1), z2 = sigm(giz1 + az1);
      float n2 = tanhf(gin1 + r2 * (an1 + bhn));
      h[1] = (1.0f - z2) * n2 + z2 * wtd1;
    }
    outh[((size_t)b0 * 512 + t) * 128 + tid] = h[0];
    outh[((size_t)b1 * 512 + t) * 128 + tid] = h[1];
    __syncthreads();  // protect wt for next iter
  }

  // last_out via mask
  {
    int p0 = 0, p1 = 0;
    for (int t = tid; t < 512; t += 128) { p0 += mask[b0 * 512 + t]; p1 += mask[b1 * 512 + t]; }
    ps[tid] = (float)p0; ps[128 + tid] = (float)p1;
    __syncthreads();
    if (tid < 2) {
      const float* pp = ps + tid * 128;
      int s = 0;
      for (int i = 0; i < 128; i++) s += (int)pp[i];
      ais[tid] = s - 1;
    }
    __syncthreads();
    int li0 = ais[0], li1 = ais[1];
    out[b0 * 128 + tid] = outh[((size_t)b0 * 512 + li0) * 128 + tid];
    out[b1 * 128 + tid] = outh[((size_t)b1 * 512 + li1) * 128 + tid];
  }
}

// ---------------- launcher ---------------------------------------------------
extern "C" void kernel_launch(void* const* d_in, const int* in_sizes, int n_in,
                              void* d_out, int out_size) {
  const float* x    = (const float*)d_in[0];
  const int*   mask = (const int*)d_in[1];
  const float* wih  = (const float*)d_in[2];
  const float* whh  = (const float*)d_in[3];
  const float* bih  = (const float*)d_in[4];
  const float* bhh  = (const float*)d_in[5];
  const float* a1w1 = (const float*)d_in[6];
  const float* a1b1 = (const float*)d_in[7];
  const float* a1w2 = (const float*)d_in[8];
  const float* a1b2 = (const float*)d_in[9];
  const float* a2w1 = (const float*)d_in[10];
  const float* a2b1 = (const float*)d_in[11];
  const float* a2w2 = (const float*)d_in[12];
  const float* a2b2 = (const float*)d_in[13];
  float* out = (float*)d_out;

  const int smem_gi = (128 * 132 + 128 * 128 + 128 * 132 + 128) * 4;
  const int smem_a2 = (128 * 132 + 64 * 128 + 640 + 64 + 16) * 4;
  const int smem_rc = (49152 + 8192 + 256 + 256 + 40) * 4 + 16;

  cudaFuncSetAttribute(k_gi,    cudaFuncAttributeMaxDynamicSharedMemorySize, smem_gi);
  cudaFuncSetAttribute(k_act2,  cudaFuncAttributeMaxDynamicSharedMemorySize, smem_a2);
  cudaFuncSetAttribute(k_recur, cudaFuncAttributeMaxDynamicSharedMemorySize, smem_rc);

  k_keys<<<4, 256>>>();
  k_gum<<<1024, 256>>>();
  k_act2<<<1024, 128, smem_a2>>>(x, a2w1, a2b1, a2w2, a2b2);
  k_gi<<<1024, 128, smem_gi>>>(x, wih, bih, bhh);
  k_recur<<<128, 128, smem_rc>>>(mask, whh, bhh, a1w1, a1b1, a1w2, a1b2, out);
}

// round 6
// speedup vs baseline: 1.3921x; 1.3916x over previous
#include <cuda_runtime.h>
#include <cstdint>

#define Bb 256
#define Tt 512

__device__ uint2 g_keys[1024];
__device__ float g_gum[1024][2560];
__device__ int   g_act2[Tt * Bb];
__device__ float g_gi[(size_t)Bb * Tt * 384];

__device__ __forceinline__ void tf2x32(uint32_t k0, uint32_t k1,
                                       uint32_t x0, uint32_t x1,
                                       uint32_t &o0, uint32_t &o1) {
  uint32_t k2 = k0 ^ k1 ^ 0x1BD11BDAu;
#define R_(r) { x0 += x1; x1 = (x1 << (r)) | (x1 >> (32 - (r))); x1 ^= x0; }
  x0 += k0; x1 += k1;
  R_(13) R_(15) R_(26) R_(6)  x0 += k1; x1 += k2 + 1u;
  R_(17) R_(29) R_(16) R_(24) x0 += k2; x1 += k0 + 2u;
  R_(13) R_(15) R_(26) R_(6)  x0 += k0; x1 += k1 + 3u;
  R_(17) R_(29) R_(16) R_(24) x0 += k1; x1 += k2 + 4u;
  R_(13) R_(15) R_(26) R_(6)  x0 += k2; x1 += k0 + 5u;
#undef R_
  o0 = x0; o1 = x1;
}

__device__ __forceinline__ float b2g(uint32_t bits) {
  float f = __uint_as_float((bits >> 9) | 0x3f800000u) - 1.0f;
  double u = (double)fmaxf(f, 1.17549435e-38f);
  return (float)(-log(-log(u)));
}

__device__ __forceinline__ float sigm(float x) { return 1.0f / (1.0f + expf(-x)); }

__global__ void k_keys() {
  int j = blockIdx.x * 256 + threadIdx.x;
  if (j >= 1024) return;
  uint32_t o0, o1;
  tf2x32(0u, 42u, 0u, (uint32_t)j, o0, o1);
  g_keys[j] = make_uint2(o0, o1);
}

__global__ void k_gum() {
  int j = blockIdx.x;
  uint2 key = g_keys[j];
  for (int p = threadIdx.x; p < 2560; p += 256) {
    uint32_t o0, o1;
    tf2x32(key.x, key.y, 0u, (uint32_t)p, o0, o1);
    g_gum[j][p] = b2g(o0 ^ o1);
  }
}

// gi GEMM: grid (1024,3), 256 thr, 128x128 tile, 8x8 micro-tile.
__global__ __launch_bounds__(256) void k_gi(const float* __restrict__ x,
                                            const float* __restrict__ wih,
                                            const float* __restrict__ bih,
                                            const float* __restrict__ bhh) {
  extern __shared__ float sm[];
  float* xs = sm;               // 128 x 132 (m-major)
  float* ws = xs + 128 * 132;   // 128 x 132 (k-major, transposed w)
  int tid = threadIdx.x;
  size_t m0 = (size_t)blockIdx.x * 128;
  int n0 = blockIdx.y * 128;
  int mr = tid >> 1, hl = tid & 1;
  {
    const float4* src = (const float4*)(x + (m0 + mr) * 128 + hl * 64);
    float4* dst = (float4*)(xs + mr * 132 + hl * 64);
#pragma unroll
    for (int i = 0; i < 16; i++) dst[i] = src[i];
  }
  {
    const float4* src = (const float4*)(wih + (size_t)(n0 + mr) * 128 + hl * 64);
#pragma unroll
    for (int i = 0; i < 16; i++) {
      float4 v = src[i];
      int kb = hl * 64 + i * 4;
      ws[(kb + 0) * 132 + mr] = v.x; ws[(kb + 1) * 132 + mr] = v.y;
      ws[(kb + 2) * 132 + mr] = v.z; ws[(kb + 3) * 132 + mr] = v.w;
    }
  }
  int tx = tid & 15, ty = tid >> 4;
  float bv[8];
#pragma unroll
  for (int j = 0; j < 8; j++) {
    int g = n0 + tx * 8 + j;
    bv[j] = bih[g] + (g < 256 ? bhh[g] : 0.0f);
  }
  __syncthreads();

  float acc[64];
#pragma unroll
  for (int i = 0; i < 8; i++)
#pragma unroll
    for (int j = 0; j < 8; j++) acc[i * 8 + j] = bv[j];
  const float* xrow = xs + ty * 8 * 132;
#pragma unroll 2
  for (int kk = 0; kk < 128; kk += 4) {
    float4 a4[8];
#pragma unroll
    for (int i = 0; i < 8; i++) a4[i] = *(const float4*)(xrow + i * 132 + kk);
#pragma unroll
    for (int dk = 0; dk < 4; dk++) {
      float4 bl = *(const float4*)(ws + (kk + dk) * 132 + tx * 8);
      float4 bh = *(const float4*)(ws + (kk + dk) * 132 + tx * 8 + 4);
#pragma unroll
      for (int i = 0; i < 8; i++) {
        float av = (dk == 0) ? a4[i].x : (dk == 1) ? a4[i].y : (dk == 2) ? a4[i].z : a4[i].w;
        acc[i*8+0] += av * bl.x; acc[i*8+1] += av * bl.y;
        acc[i*8+2] += av * bl.z; acc[i*8+3] += av * bl.w;
        acc[i*8+4] += av * bh.x; acc[i*8+5] += av * bh.y;
        acc[i*8+6] += av * bh.z; acc[i*8+7] += av * bh.w;
      }
    }
  }
#pragma unroll
  for (int i = 0; i < 8; i++) {
    float* dst = g_gi + (m0 + ty * 8 + i) * 384 + n0 + tx * 8;
    *(float4*)(dst)     = make_float4(acc[i*8+0], acc[i*8+1], acc[i*8+2], acc[i*8+3]);
    *(float4*)(dst + 4) = make_float4(acc[i*8+4], acc[i*8+5], acc[i*8+6], acc[i*8+7]);
  }
}

__global__ __launch_bounds__(128, 1) void k_act2(const float* __restrict__ x,
                                                 const float* __restrict__ w1,
                                                 const float* __restrict__ b1,
                                                 const float* __restrict__ w2,
                                                 const float* __restrict__ b2) {
  extern __shared__ float sm[];
  float* xs  = sm;
  float* w1s = xs + 128 * 132;
  float* w2s = w1s + 64 * 128;
  float* b1s = w2s + 640;
  float* b2s = b1s + 64;
  int tid = threadIdx.x;
  size_t row0 = (size_t)blockIdx.x * 128;
  const float4* xg = (const float4*)(x + row0 * 128);
  for (int i = tid; i < 128 * 32; i += 128) {
    int r = i >> 5, c = i & 31;
    ((float4*)(xs + r * 132))[c] = xg[i];
  }
  for (int i = tid; i < 64 * 32; i += 128) ((float4*)w1s)[i] = ((const float4*)w1)[i];
  for (int i = tid; i < 640; i += 128) w2s[i] = w2[i];
  if (tid < 64) b1s[tid] = b1[tid];
  if (tid < 10) b2s[tid] = b2[tid];
  __syncthreads();
  float acc[64];
#pragma unroll
  for (int u = 0; u < 64; u++) acc[u] = b1s[u];
  const float4* xr = (const float4*)(xs + tid * 132);
  for (int c = 0; c < 32; c++) {
    float4 xv = xr[c];
#pragma unroll
    for (int u = 0; u < 64; u++) {
      float4 wv = ((const float4*)w1s)[u * 32 + c];
      acc[u] += xv.x * wv.x + xv.y * wv.y + xv.z * wv.z + xv.w * wv.w;
    }
  }
#pragma unroll
  for (int u = 0; u < 64; u++) acc[u] = tanhf(acc[u]);
  size_t row = row0 + tid;
  int b = (int)(row >> 9), t = (int)(row & 511);
  const float* gg = g_gum[2 * t + 1] + b * 10;
  float best = -1e30f; int bi = 0;
#pragma unroll
  for (int a = 0; a < 10; a++) {
    float lg = b2s[a];
#pragma unroll
    for (int u = 0; u < 64; u++) lg += acc[u] * w2s[a * 64 + u];
    float v = lg + gg[a];
    if (v > best) { best = v; bi = a; }
  }
  g_act2[t * 256 + b] = bi;
}

// recurrent: 128 CTAs x 256 thr. Thread (bb=tid>>7, d=tid&127).
__global__ __launch_bounds__(256, 1) void k_recur(const int* __restrict__ mask,
                                                  const float* __restrict__ whh,
                                                  const float* __restrict__ bhh,
                                                  const float* __restrict__ a1w1,
                                                  const float* __restrict__ a1b1,
                                                  const float* __restrict__ a1w2,
                                                  const float* __restrict__ a1b2,
                                                  float* __restrict__ out) {
  extern __shared__ float sm[];
  float* wsp = sm;               // 384 x 132 padded w_hh
  float* wt  = wsp + 384 * 132;  // [2][128]
  float* ps  = wt + 256;         // [256]
  float* ex0 = ps + 256;         // 128*3
  float* ex1 = ex0 + 384;        // 128*3
  int*   ais = (int*)(ex1 + 384);

  int tid = threadIdx.x;
  int d = tid & 127, bb = tid >> 7;
  int wid = tid >> 5, lane = tid & 31;
  int b0 = blockIdx.x * 2, bg = b0 + bb;
  float* outh = out + (size_t)Bb * 128;

  for (int i = tid; i < 384 * 128; i += 256) {
    int g = i >> 7, k = i & 127;
    wsp[g * 132 + k] = whh[i];
  }
  float w1r[64];
  {
    int u = tid & 63, hf = (tid >> 6) & 1;
    const float4* src = (const float4*)(a1w1 + u * 128 + hf * 64);
#pragma unroll
    for (int k = 0; k < 16; k++) {
      float4 v = src[k];
      w1r[4*k] = v.x; w1r[4*k+1] = v.y; w1r[4*k+2] = v.z; w1r[4*k+3] = v.w;
    }
  }
  float bhn = bhh[256 + d];
  float w2a[10], w2b[10], b2r[10], b1a = 0.0f, b1b = 0.0f;
#pragma unroll
  for (int a = 0; a < 10; a++) { w2a[a] = 0.0f; w2b[a] = 0.0f; b2r[a] = 0.0f; }
  if (wid < 2) {
    b1a = a1b1[lane]; b1b = a1b1[lane + 32];
#pragma unroll
    for (int a = 0; a < 10; a++) {
      w2a[a] = a1w2[a * 64 + lane];
      w2b[a] = a1w2[a * 64 + lane + 32];
      b2r[a] = a1b2[a];
    }
  }
  __syncthreads();

  float h, buf[10];
#pragma unroll
  for (int q = 0; q < 10; q++) buf[q] = 0.0f;
  {
    size_t rr = ((size_t)bg * 512) * 384;
    float gir = g_gi[rr + d], giz = g_gi[rr + 128 + d], gin = g_gi[rr + 256 + d];
    float r = sigm(gir), z = sigm(giz);
    h = (1.0f - z) * tanhf(gin + r * bhn);
    outh[((size_t)bg * 512) * 128 + d] = h;
  }

  float g1p[10]; int a2p = 0;
#pragma unroll
  for (int a = 0; a < 10; a++) g1p[a] = 0.0f;
  if (wid < 2 && lane == 0) {
    const float* gg = g_gum[2] + (b0 + wid) * 10;
#pragma unroll
    for (int a = 0; a < 10; a++) g1p[a] = gg[a];
    a2p = g_act2[256 + (b0 + wid)];
  }

  for (int t = 1; t < 512; t++) {
    size_t rg = ((size_t)bg * 512 + t) * 384;
    float gir = g_gi[rg + d], giz = g_gi[rg + 128 + d], gin = g_gi[rg + 256 + d];
    {
      float s = h;
#pragma unroll
      for (int q = 0; q < 9; q++) { buf[q] = buf[q + 1]; s += buf[q]; }
      buf[9] = h;
      wt[bb * 128 + d] = s / 10.0f;
    }
    __syncthreads();                                   // A
    {
      int hf = (tid >> 6) & 1, zb = tid >> 7;
      const float4* mv = (const float4*)(wt + zb * 128 + hf * 64);
      float p = 0.0f;
#pragma unroll
      for (int k = 0; k < 16; k++) {
        float4 m4 = mv[k];
        p += m4.x*w1r[4*k] + m4.y*w1r[4*k+1] + m4.z*w1r[4*k+2] + m4.w*w1r[4*k+3];
      }
      ps[tid] = p;
    }
    float g1n[10]; int a2n = 0;
#pragma unroll
    for (int a = 0; a < 10; a++) g1n[a] = 0.0f;
    if (wid < 2 && lane == 0 && t < 511) {
      const float* gg = g_gum[2 * (t + 1)] + (b0 + wid) * 10;
#pragma unroll
      for (int a = 0; a < 10; a++) g1n[a] = gg[a];
      a2n = g_act2[(t + 1) * 256 + (b0 + wid)];
    }
    __syncthreads();                                   // B
    if (wid < 2) {
      const float* base = ps + wid * 128;
      float zA = tanhf(base[lane] + base[64 + lane] + b1a);
      float zB = tanhf(base[32 + lane] + base[96 + lane] + b1b);
      float lp[10];
#pragma unroll
      for (int a = 0; a < 10; a++) lp[a] = zA * w2a[a] + zB * w2b[a];
#pragma unroll
      for (int off = 16; off > 0; off >>= 1)
#pragma unroll
        for (int a = 0; a < 10; a++) lp[a] += __shfl_down_sync(0xffffffffu, lp[a], off);
      if (lane == 0) {
        float best = -1e30f; int bi = 0;
#pragma unroll
        for (int a = 0; a < 10; a++) {
          float v = lp[a] + b2r[a] + g1p[a];
          if (v > best) { best = v; bi = a; }
        }
        ais[wid] = bi; ais[2 + wid] = a2p;
      }
    }
    __syncthreads();                                   // C
    float wtd;
    {
      int aa = ais[bb], a2 = ais[2 + bb];
      float sa = buf[0], sb2 = buf[0];
#pragma unroll
      for (int q = 1; q < 10; q++) {
        if (aa == q) sa = buf[q];
        if (a2 == q) sb2 = buf[q];
      }
      wtd = 0.25f * (sa + sb2) + 0.5f * h;
      wt[bb * 128 + d] = wtd;
    }
    if (wid < 2 && lane == 0) {
#pragma unroll
      for (int a = 0; a < 10; a++) g1p[a] = g1n[a];
      a2p = a2n;
    }
    __syncthreads();                                   // D
    float ar0 = 0, az0 = 0, an0 = 0, ar1 = 0, az1 = 0, an1 = 0;
    {
      int k0 = bb * 64;
      const float4* r0 = (const float4*)(wsp + d * 132 + k0);
      const float4* r1 = (const float4*)(wsp + (d + 128) * 132 + k0);
      const float4* r2 = (const float4*)(wsp + (d + 256) * 132 + k0);
      const float4* va = (const float4*)(wt + k0);
      const float4* vb = (const float4*)(wt + 128 + k0);
#pragma unroll 4
      for (int c = 0; c < 16; c++) {
        float4 wr = r0[c], wz = r1[c], wn = r2[c];
        float4 v0 = va[c], v1 = vb[c];
        ar0 += wr.x*v0.x + wr.y*v0.y + wr.z*v0.z + wr.w*v0.w;
        az0 += wz.x*v0.x + wz.y*v0.y + wz.z*v0.z + wz.w*v0.w;
        an0 += wn.x*v0.x + wn.y*v0.y + wn.z*v0.z + wn.w*v0.w;
        ar1 += wr.x*v1.x + wr.y*v1.y + wr.z*v1.z + wr.w*v1.w;
        az1 += wz.x*v1.x + wz.y*v1.y + wz.z*v1.z + wz.w*v1.w;
        an1 += wn.x*v1.x + wn.y*v1.y + wn.z*v1.z + wn.w*v1.w;
      }
    }
    if (bb == 0) { ex1[d*3] = ar1; ex1[d*3+1] = az1; ex1[d*3+2] = an1; }
    else         { ex0[d*3] = ar0; ex0[d*3+1] = az0; ex0[d*3+2] = an0; }
    __syncthreads();                                   // E
    float gr, gz, gn;
    if (bb == 0) { gr = ar0 + ex0[d*3]; gz = az0 + ex0[d*3+1]; gn = an0 + ex0[d*3+2]; }
    else         { gr = ex1[d*3] + ar1; gz = ex1[d*3+1] + az1; gn = ex1[d*3+2] + an1; }
    {
      float r = sigm(gir + gr), z = sigm(giz + gz);
      float n = tanhf(gin + r * (gn + bhn));
      h = (1.0f - z) * n + z * wtd;
    }
    outh[((size_t)bg * 512 + t) * 128 + d] = h;
  }

  __syncthreads();
  {
    int cnt = 0;
    for (int t = d; t < 512; t += 128) cnt += mask[bg * 512 + t];
    ps[tid] = (float)cnt;
    __syncthreads();
    if (tid < 2) {
      int s = 0;
      for (int i = 0; i < 128; i++) s += (int)ps[tid * 128 + i];
      ais[tid] = s - 1;
    }
    __syncthreads();
    int li = ais[bb];
    out[bg * 128 + d] = outh[((size_t)bg * 512 + li) * 128 + d];
  }
}

extern "C" void kernel_launch(void* const* d_in, const int* in_sizes, int n_in,
                              void* d_out, int out_size) {
  const float* x    = (const float*)d_in[0];
  const int*   mask = (const int*)d_in[1];
  const float* wih  = (const float*)d_in[2];
  const float* whh  = (const float*)d_in[3];
  const float* bih  = (const float*)d_in[4];
  const float* bhh  = (const float*)d_in[5];
  const float* a1w1 = (const float*)d_in[6];
  const float* a1b1 = (const float*)d_in[7];
  const float* a1w2 = (const float*)d_in[8];
  const float* a1b2 = (const float*)d_in[9];
  const float* a2w1 = (const float*)d_in[10];
  const float* a2b1 = (const float*)d_in[11];
  const float* a2w2 = (const float*)d_in[12];
  const float* a2b2 = (const float*)d_in[13];
  float* out = (float*)d_out;

  const int smem_gi = 2 * 128 * 132 * 4;
  const int smem_a2 = (128 * 132 + 64 * 128 + 640 + 64 + 16) * 4;
  const int smem_rc = (384 * 132 + 256 + 256 + 384 + 384) * 4 + 16;

  cudaFuncSetAttribute(k_gi,    cudaFuncAttributeMaxDynamicSharedMemorySize, smem_gi);
  cudaFuncSetAttribute(k_act2,  cudaFuncAttributeMaxDynamicSharedMemorySize, smem_a2);
  cudaFuncSetAttribute(k_recur, cudaFuncAttributeMaxDynamicSharedMemorySize, smem_rc);

  k_keys<<<4, 256>>>();
  k_gum<<<1024, 256>>>();
  k_act2<<<1024, 128, smem_a2>>>(x, a2w1, a2b1, a2w2, a2b2);
  k_gi<<<dim3(1024, 3), 256, smem_gi>>>(x, wih, bih, bhh);
  k_recur<<<128, 256, smem_rc>>>(mask, whh, bhh, a1w1, a1b1, a1w2, a1b2, out);
}